// round 12
// baseline (speedup 1.0000x reference)
#include <cuda_runtime.h>
#include <cuda_bf16.h>
#include <math.h>
#include <stdint.h>

#define B_  4
#define T_  2048
#define D_  512
#define H_  8
#define P_  16
#define DH_ 64
#define C_  512
#define HF_ 64
#define WF_ 64
#define HW_ (HF_*WF_)
#define RADIUS_ 0.08f
#define M_BT (B_*T_)
#define NQ_ (H_*P_*2 + H_*P_)

typedef __nv_bfloat16 bf16;

// ---- scratch: fp32 ----
__device__ float g_v    [(size_t)B_*HW_*D_];
__device__ float g_proj [(size_t)M_BT*NQ_];
__device__ float g_bq   [NQ_];
// ---- scratch: bf16 hi/lo operand pairs ----
__device__ bf16 g_fmh[(size_t)B_*HW_*C_], g_fml[(size_t)B_*HW_*C_];  // fmapT split
__device__ bf16 g_qh [(size_t)M_BT*D_],   g_ql [(size_t)M_BT*D_];    // q split
__device__ bf16 g_ch [(size_t)M_BT*D_],   g_cl [(size_t)M_BT*D_];    // ctx split
__device__ bf16 g_Wvh[(size_t)D_*C_],     g_Wvl[(size_t)D_*C_];      // WvT split
__device__ bf16 g_Woh[(size_t)D_*D_],     g_Wol[(size_t)D_*D_];      // WoutT split
__device__ bf16 g_Wqh[(size_t)NQ_*D_],    g_Wql[(size_t)NQ_*D_];     // WqT split

__device__ __forceinline__ void split1(float x, bf16& h, bf16& l) {
    h = __float2bfloat16(x);
    l = __float2bfloat16(x - __bfloat162float(h));
}

// ============================================================
// fmap transpose + split: [B][C][HW] fp32 -> [B][HW][C] bf16 hi/lo
// ============================================================
__global__ void transpose_split_fmap(const float* __restrict__ in) {
    __shared__ float tile[32][33];
    const int b = blockIdx.z;
    const size_t bi = (size_t)b * C_ * HW_;
    const size_t bo = (size_t)b * HW_ * C_;
    const int c0 = blockIdx.x * 32, r0 = blockIdx.y * 32;   // c0: HW pos, r0: channel
    const int tx = threadIdx.x, ty = threadIdx.y;
    #pragma unroll
    for (int i = 0; i < 32; i += 8)
        tile[ty + i][tx] = in[bi + (size_t)(r0 + ty + i) * HW_ + c0 + tx];
    __syncthreads();
    #pragma unroll
    for (int i = 0; i < 32; i += 8) {
        float v = tile[tx][ty + i];
        bf16 h, l; split1(v, h, l);
        const size_t o = bo + (size_t)(c0 + ty + i) * C_ + r0 + tx;
        g_fmh[o] = h; g_fml[o] = l;
    }
}

// ============================================================
// Weight transposes + split + bias concat (one launch)
// ============================================================
__global__ void prep_weights(const float* __restrict__ Wv,  const float* __restrict__ Wout,
                             const float* __restrict__ Woff, const float* __restrict__ Ww,
                             const float* __restrict__ boff, const float* __restrict__ bw)
{
    __shared__ float tile[32][33];
    const int z = blockIdx.z;
    const float* in; bf16 *oh, *ol; int Ccols; size_t obase = 0;
    if      (z == 0) { in = Wv;   oh = g_Wvh; ol = g_Wvl; Ccols = 512; }
    else if (z == 1) { in = Wout; oh = g_Woh; ol = g_Wol; Ccols = 512; }
    else if (z == 2) { in = Woff; oh = g_Wqh; ol = g_Wql; Ccols = 256; }
    else             { in = Ww;   oh = g_Wqh; ol = g_Wql; Ccols = 128; obase = (size_t)256 * D_; }
    const int tx = threadIdx.x, ty = threadIdx.y;

    if (z == 3 && blockIdx.x == 0 && blockIdx.y == 0) {
        const int idx0 = ty * 32 + tx;
        for (int i = idx0; i < NQ_; i += 256)
            g_bq[i] = (i < 256) ? boff[i] : bw[i - 256];
    }

    const int c0 = blockIdx.x * 32, r0 = blockIdx.y * 32;
    if (c0 >= Ccols) return;
    #pragma unroll
    for (int i = 0; i < 32; i += 8)
        tile[ty + i][tx] = in[(size_t)(r0 + ty + i) * Ccols + c0 + tx];
    __syncthreads();
    #pragma unroll
    for (int i = 0; i < 32; i += 8) {
        float v = tile[tx][ty + i];
        bf16 h, l; split1(v, h, l);
        const size_t o = obase + (size_t)(c0 + ty + i) * D_ + r0 + tx;
        oh[o] = h; ol[o] = l;
    }
}

// ============================================================
// q split: fp32 [M][512] -> bf16 hi/lo
// ============================================================
__global__ void split_q(const float* __restrict__ q) {
    const size_t i = ((size_t)blockIdx.x * 256 + threadIdx.x) * 4;
    float4 v = *(const float4*)(q + i);
    bf16 h0,h1,h2,h3,l0,l1,l2,l3;
    split1(v.x,h0,l0); split1(v.y,h1,l1); split1(v.z,h2,l2); split1(v.w,h3,l3);
    __nv_bfloat162 H01={h0,h1}, H23={h2,h3}, L01={l0,l1}, L23={l2,l3};
    *(uint2*)(g_qh + i) = make_uint2(*(uint32_t*)&H01, *(uint32_t*)&H23);
    *(uint2*)(g_ql + i) = make_uint2(*(uint32_t*)&L01, *(uint32_t*)&L23);
}

// ============================================================
// bf16x3 GEMM, pre-split operands, cp.async 3-stage pipeline.
// C[m,n] = sum_k A[m,k]*BT[n,k] (+bias). CTA 128x64, 8 warps (4m x 2n).
// ============================================================
#define KC  32
#define KPB 40
#define SSTA (128 * KPB)
#define SSTB (64 * KPB)
#define STG (2 * SSTA + 2 * SSTB)
#define OFF_AH 0
#define OFF_AL SSTA
#define OFF_BH (2 * SSTA)
#define OFF_BL (2 * SSTA + SSTB)
#define NSTAGE 3
#define GSMEM (NSTAGE * STG * 2)     // 92160 B

#define MMA_BF16(acc, a, b) \
    asm volatile( \
        "mma.sync.aligned.m16n8k16.row.col.f32.bf16.bf16.f32 " \
        "{%0,%1,%2,%3}, {%4,%5,%6,%7}, {%8,%9}, {%0,%1,%2,%3};" \
        : "+f"((acc)[0]), "+f"((acc)[1]), "+f"((acc)[2]), "+f"((acc)[3]) \
        : "r"((a)[0]), "r"((a)[1]), "r"((a)[2]), "r"((a)[3]), \
          "r"((b)[0]), "r"((b)[1]))

#define LDM_X4(r, addr) \
    asm volatile("ldmatrix.sync.aligned.m8n8.x4.shared.b16 {%0,%1,%2,%3}, [%4];" \
        : "=r"((r)[0]), "=r"((r)[1]), "=r"((r)[2]), "=r"((r)[3]) : "r"(addr))
#define LDM_X2(r, addr) \
    asm volatile("ldmatrix.sync.aligned.m8n8.x2.shared.b16 {%0,%1}, [%2];" \
        : "=r"((r)[0]), "=r"((r)[1]) : "r"(addr))

#define CP16(dst, src) \
    asm volatile("cp.async.cg.shared.global [%0], [%1], 16;" :: "r"(dst), "l"(src))
#define CP_COMMIT() asm volatile("cp.async.commit_group;" ::: "memory")
#define CP_WAIT2()  asm volatile("cp.async.wait_group 2;" ::: "memory")

__global__ void __launch_bounds__(256, 2) gemm_split(
    const bf16* __restrict__ Ah, const bf16* __restrict__ Al,
    const bf16* __restrict__ Bh, const bf16* __restrict__ Bl,
    const float* __restrict__ bias, float* __restrict__ Cout,
    int N, int K, size_t a_bstride, size_t c_bstride)
{
    extern __shared__ __align__(16) bf16 smem[];

    const int tid = threadIdx.x;
    const int warp = tid >> 5, lane = tid & 31;
    const int g = lane >> 2, t = lane & 3;
    const int warpM = (warp >> 1) * 32;
    const int warpN = (warp & 1) * 32;
    const int m0 = blockIdx.x * 128, n0 = blockIdx.y * 64;
    const bf16* Abh = Ah + blockIdx.z * a_bstride;
    const bf16* Abl = Al + blockIdx.z * a_bstride;
    float* Cb = Cout + blockIdx.z * c_bstride;

    // cp.async mapping: A chunks c=tid(+256): row=c>>2, q=c&3 ; B chunks: tid<256
    const int arow0 = tid >> 2, aq = tid & 3;     // rows 0..63 (j=0), 64..127 (j=1)
    const int brow  = tid >> 2 & 63;              // 0..63

    const int aRow = (lane & 7) + ((lane >> 3) & 1) * 8;
    const int aK8  = (lane >> 4) * 8;
    const int bRow = lane & 7;
    const int bK8  = ((lane >> 3) & 1) * 8;

    const uint32_t smem_base = (uint32_t)__cvta_generic_to_shared(smem);
    const uint32_t aLaneOff = (uint32_t)((warpM + aRow) * KPB + aK8) * 2;
    const uint32_t bLaneOff = (uint32_t)((warpN + bRow) * KPB + bK8) * 2;

    float acc[2][4][4];
    #pragma unroll
    for (int a = 0; a < 2; a++)
        #pragma unroll
        for (int b = 0; b < 4; b++)
            #pragma unroll
            for (int c = 0; c < 4; c++) acc[a][b][c] = 0.f;

    const int ntiles = K / KC;

    // --- async stage issue ---
    auto issue = [&](int stage, int k0) {
        const uint32_t sb = smem_base + (uint32_t)(stage * STG) * 2;
        #pragma unroll
        for (int j = 0; j < 2; j++) {
            const int row = arow0 + j * 64;
            const size_t so = (size_t)(m0 + row) * K + k0 + aq * 8;
            const uint32_t d = sb + (uint32_t)(row * KPB + aq * 8) * 2;
            CP16(d + OFF_AH * 2, Abh + so);
            CP16(d + OFF_AL * 2, Abl + so);
        }
        {
            const size_t so = (size_t)(n0 + brow) * K + k0 + aq * 8;
            const uint32_t d = sb + (uint32_t)(brow * KPB + aq * 8) * 2;
            CP16(d + OFF_BH * 2, Bh + so);
            CP16(d + OFF_BL * 2, Bl + so);
        }
    };

    issue(0, 0); CP_COMMIT();
    if (ntiles > 1) issue(1, KC);
    CP_COMMIT();

    for (int i = 0; i < ntiles; i++) {
        if (i + 2 < ntiles) issue((i + 2) % NSTAGE, (i + 2) * KC);
        CP_COMMIT();
        CP_WAIT2();
        __syncthreads();

        const uint32_t stg = smem_base + (uint32_t)((i % NSTAGE) * STG) * 2;
        const uint32_t AhB = stg + OFF_AH * 2 + aLaneOff;
        const uint32_t AlB = stg + OFF_AL * 2 + aLaneOff;
        const uint32_t BhB = stg + OFF_BH * 2 + bLaneOff;
        const uint32_t BlB = stg + OFF_BL * 2 + bLaneOff;

        #pragma unroll
        for (int kk = 0; kk < 2; kk++) {
            const uint32_t kOff = (uint32_t)(kk * 16) * 2;
            uint32_t ah[2][4], al[2][4], bh[4][2], bl[4][2];
            #pragma unroll
            for (int mt = 0; mt < 2; mt++) {
                const uint32_t mo = (uint32_t)(mt * 16 * KPB) * 2 + kOff;
                LDM_X4(ah[mt], AhB + mo);
                LDM_X4(al[mt], AlB + mo);
            }
            #pragma unroll
            for (int nt = 0; nt < 4; nt++) {
                const uint32_t no = (uint32_t)(nt * 8 * KPB) * 2 + kOff;
                LDM_X2(bh[nt], BhB + no);
                LDM_X2(bl[nt], BlB + no);
            }
            #pragma unroll
            for (int mt = 0; mt < 2; mt++)
                #pragma unroll
                for (int nt = 0; nt < 4; nt++) {
                    MMA_BF16(acc[mt][nt], ah[mt], bh[nt]);
                    MMA_BF16(acc[mt][nt], ah[mt], bl[nt]);
                    MMA_BF16(acc[mt][nt], al[mt], bh[nt]);
                }
        }
        __syncthreads();
    }

    #pragma unroll
    for (int mt = 0; mt < 2; mt++) {
        const int r0 = m0 + warpM + mt * 16 + g;
        #pragma unroll
        for (int nt = 0; nt < 4; nt++) {
            const int cc = n0 + warpN + nt * 8 + 2 * t;
            float b0 = bias ? bias[cc] : 0.f;
            float b1 = bias ? bias[cc + 1] : 0.f;
            float2 o0 = make_float2(acc[mt][nt][0] + b0, acc[mt][nt][1] + b1);
            float2 o1 = make_float2(acc[mt][nt][2] + b0, acc[mt][nt][3] + b1);
            *(float2*)(Cb + (size_t)r0 * N + cc)       = o0;
            *(float2*)(Cb + (size_t)(r0 + 8) * N + cc) = o1;
        }
    }
}

// ============================================================
// Softmax + bilinear gather -> ctx written as bf16 hi/lo
// ============================================================
__global__ void sample_kernel(const float* __restrict__ ref_xy)
{
    const int bt = blockIdx.x;
    const int b  = bt >> 11;
    const int h  = threadIdx.x >> 5;
    const int lane = threadIdx.x & 31;

    const float* vb = g_v + (size_t)b * HW_ * D_;
    const float rx = ref_xy[(size_t)bt * 2 + 0];
    const float ry = ref_xy[(size_t)bt * 2 + 1];

    const float* pr = g_proj + (size_t)bt * NQ_;

    float wv = -INFINITY, ox = 0.f, oy = 0.f;
    if (lane < P_) {
        wv = pr[256 + h * P_ + lane];
        ox = pr[(h * P_ + lane) * 2 + 0];
        oy = pr[(h * P_ + lane) * 2 + 1];
    }
    float m = wv;
    #pragma unroll
    for (int o = 8; o >= 1; o >>= 1) m = fmaxf(m, __shfl_xor_sync(0xffffffffu, m, o));
    float e = (lane < P_) ? __expf(wv - m) : 0.f;
    float s = e;
    #pragma unroll
    for (int o = 8; o >= 1; o >>= 1) s += __shfl_xor_sync(0xffffffffu, s, o);
    const float aw = (lane < P_) ? (e / s) : 0.f;

    const float ix = (rx + RADIUS_ * ox) * (float)(WF_ - 1);
    const float iy = (ry + RADIUS_ * oy) * (float)(HF_ - 1);
    const float fx0 = floorf(ix), fy0 = floorf(iy);
    const int   x0 = (int)fx0,   y0 = (int)fy0;
    const float fx = ix - fx0,   fy = iy - fy0;

    int   idxc[4];
    float wc[4];
    {
        const int x1 = x0 + 1, y1 = y0 + 1;
        const int xs[4] = {x0, x1, x0, x1};
        const int ys[4] = {y0, y0, y1, y1};
        const float ww[4] = {(1.f - fx) * (1.f - fy), fx * (1.f - fy),
                             (1.f - fx) * fy,         fx * fy};
        #pragma unroll
        for (int c = 0; c < 4; c++) {
            const bool valid = (xs[c] >= 0) & (xs[c] < WF_) & (ys[c] >= 0) & (ys[c] < HF_);
            const int xc = min(max(xs[c], 0), WF_ - 1);
            const int yc = min(max(ys[c], 0), HF_ - 1);
            idxc[c] = yc * WF_ + xc;
            wc[c]   = valid ? (ww[c] * aw) : 0.f;
        }
    }

    float acc0 = 0.f, acc1 = 0.f;
    const int hbase = h * DH_;
    #pragma unroll 4
    for (int p = 0; p < P_; p++) {
        #pragma unroll
        for (int c = 0; c < 4; c++) {
            const int   idx = __shfl_sync(0xffffffffu, idxc[c], p);
            const float w   = __shfl_sync(0xffffffffu, wc[c],   p);
            if (w != 0.f) {
                const float* vp = vb + (size_t)idx * D_ + hbase;
                acc0 += w * vp[lane];
                acc1 += w * vp[lane + 32];
            }
        }
    }
    const size_t co = (size_t)bt * D_ + hbase;
    bf16 h0, l0, h1, l1;
    split1(acc0, h0, l0);
    split1(acc1, h1, l1);
    g_ch[co + lane]      = h0;  g_cl[co + lane]      = l0;
    g_ch[co + lane + 32] = h1;  g_cl[co + lane + 32] = l1;
}

// ============================================================
extern "C" void kernel_launch(void* const* d_in, const int* in_sizes, int n_in,
                              void* d_out, int out_size)
{
    const float* q      = (const float*)d_in[0];
    const float* fmap   = (const float*)d_in[1];
    const float* ref_xy = (const float*)d_in[2];
    const float* Wv     = (const float*)d_in[3];
    const float* W_off  = (const float*)d_in[4];
    const float* b_off  = (const float*)d_in[5];
    const float* W_w    = (const float*)d_in[6];
    const float* b_w    = (const float*)d_in[7];
    const float* W_out  = (const float*)d_in[8];
    const float* b_out  = (const float*)d_in[9];
    float* out = (float*)d_out;

    float *v, *proj, *bq;
    bf16 *fmh, *fml, *qh, *ql, *ch, *cl, *Wvh, *Wvl, *Woh, *Wol, *Wqh, *Wql;
    cudaGetSymbolAddress((void**)&v,    g_v);
    cudaGetSymbolAddress((void**)&proj, g_proj);
    cudaGetSymbolAddress((void**)&bq,   g_bq);
    cudaGetSymbolAddress((void**)&fmh,  g_fmh);  cudaGetSymbolAddress((void**)&fml, g_fml);
    cudaGetSymbolAddress((void**)&qh,   g_qh);   cudaGetSymbolAddress((void**)&ql,  g_ql);
    cudaGetSymbolAddress((void**)&ch,   g_ch);   cudaGetSymbolAddress((void**)&cl,  g_cl);
    cudaGetSymbolAddress((void**)&Wvh,  g_Wvh);  cudaGetSymbolAddress((void**)&Wvl, g_Wvl);
    cudaGetSymbolAddress((void**)&Woh,  g_Woh);  cudaGetSymbolAddress((void**)&Wol, g_Wol);
    cudaGetSymbolAddress((void**)&Wqh,  g_Wqh);  cudaGetSymbolAddress((void**)&Wql, g_Wql);

    cudaFuncSetAttribute(gemm_split, cudaFuncAttributeMaxDynamicSharedMemorySize, GSMEM);

    // L1: fmap transpose + split
    transpose_split_fmap<<<dim3(HW_ / 32, C_ / 32, B_), dim3(32, 8)>>>(fmap);
    // L2: weight transposes + split + bias
    prep_weights<<<dim3(16, 16, 4), dim3(32, 8)>>>(Wv, W_out, W_off, W_w, b_off, b_w);
    // L3: q split
    split_q<<<(M_BT * D_ / 4) / 256, 256>>>(q);

    // L4 (K1): v[b] = fmapT[b] @ Wv
    gemm_split<<<dim3(HW_ / 128, D_ / 64, B_), 256, GSMEM>>>(
        fmh, fml, Wvh, Wvl, (const float*)0, v, D_, C_,
        (size_t)HW_ * C_, (size_t)HW_ * D_);

    // L5 (K2): proj = q @ [W_off|W_w] + bias
    gemm_split<<<dim3(M_BT / 128, NQ_ / 64, 1), 256, GSMEM>>>(
        qh, ql, Wqh, Wql, bq, proj, NQ_, D_, 0, 0);

    // L6: softmax + bilinear gather -> ctx (split)
    sample_kernel<<<M_BT, H_ * 32>>>(ref_xy);

    // L7 (K4): out = ctx @ W_out + b_out
    gemm_split<<<dim3(M_BT / 128, D_ / 64, 1), 256, GSMEM>>>(
        ch, cl, Woh, Wol, b_out, out, D_, D_, 0, 0);
}

// round 15
// speedup vs baseline: 1.0808x; 1.0808x over previous
#include <cuda_runtime.h>
#include <cuda_bf16.h>
#include <cuda_fp16.h>
#include <math.h>
#include <stdint.h>

#define B_  4
#define T_  2048
#define D_  512
#define H_  8
#define P_  16
#define DH_ 64
#define C_  512
#define HF_ 64
#define WF_ 64
#define HW_ (HF_*WF_)
#define RADIUS_ 0.08f
#define M_BT (B_*T_)
#define NQ_ (H_*P_*2 + H_*P_)

typedef __nv_bfloat16 bf16;

// ---- scratch ----
__device__ __half g_v   [(size_t)B_*HW_*D_];     // value buffer in fp16 (written by K1)
__device__ float g_proj [(size_t)M_BT*NQ_];
__device__ float g_ctx  [(size_t)M_BT*D_];
__device__ float g_fmapT[(size_t)B_*HW_*C_];
__device__ float g_WvT  [(size_t)D_*C_];
__device__ float g_WoutT[(size_t)D_*D_];
__device__ float g_WqT  [(size_t)NQ_*D_];
__device__ float g_bq   [NQ_];

// ============================================================
// fmap transpose: [B][C][HW] -> [B][HW][C]
// ============================================================
__global__ void transpose_kernel(const float* __restrict__ in, float* __restrict__ out,
                                 int R, int C) {
    __shared__ float tile[32][33];
    const size_t bo = (size_t)blockIdx.z * R * C;
    const int c0 = blockIdx.x * 32, r0 = blockIdx.y * 32;
    const int tx = threadIdx.x, ty = threadIdx.y;
    #pragma unroll
    for (int i = 0; i < 32; i += 8)
        tile[ty + i][tx] = in[bo + (size_t)(r0 + ty + i) * C + c0 + tx];
    __syncthreads();
    #pragma unroll
    for (int i = 0; i < 32; i += 8)
        out[bo + (size_t)(c0 + ty + i) * R + r0 + tx] = tile[tx][ty + i];
}

// ============================================================
// Weight transposes + bias concat (one launch)
// ============================================================
__global__ void prep_weights(const float* __restrict__ Wv,  const float* __restrict__ Wout,
                             const float* __restrict__ Woff, const float* __restrict__ Ww,
                             const float* __restrict__ boff, const float* __restrict__ bw)
{
    __shared__ float tile[32][33];
    const int z = blockIdx.z;
    const float* in; float* out; int Ccols;
    if      (z == 0) { in = Wv;   out = g_WvT;            Ccols = 512; }
    else if (z == 1) { in = Wout; out = g_WoutT;          Ccols = 512; }
    else if (z == 2) { in = Woff; out = g_WqT;            Ccols = 256; }
    else             { in = Ww;   out = g_WqT + 256 * D_; Ccols = 128; }
    const int R = 512;
    const int tx = threadIdx.x, ty = threadIdx.y;

    if (z == 3 && blockIdx.x == 0 && blockIdx.y == 0) {
        const int idx0 = ty * 32 + tx;
        for (int i = idx0; i < NQ_; i += 256)
            g_bq[i] = (i < 256) ? boff[i] : bw[i - 256];
    }

    const int c0 = blockIdx.x * 32, r0 = blockIdx.y * 32;
    if (c0 >= Ccols) return;
    #pragma unroll
    for (int i = 0; i < 32; i += 8)
        tile[ty + i][tx] = in[(size_t)(r0 + ty + i) * Ccols + c0 + tx];
    __syncthreads();
    #pragma unroll
    for (int i = 0; i < 32; i += 8)
        out[(size_t)(c0 + ty + i) * R + r0 + tx] = tile[tx][ty + i];
}

// ============================================================
// bf16x3 split GEMM, 256 threads (8 warps, 4m x 2n), warp tile 32x32.
// CTA tile 128(M) x 64(N), k-chunk 32, 2 CTAs/SM, pipelined iteration.
// Output: fp32 (Cout) or fp16 (Cout16) when Cout16 != nullptr.
// ============================================================
#define KC  32
#define KPB 40
#define SSTA (128 * KPB)
#define SSTB (64 * KPB)
#define STG (2 * SSTA + 2 * SSTB)
#define OFF_AH 0
#define OFF_AL SSTA
#define OFF_BH (2 * SSTA)
#define OFF_BL (2 * SSTA + SSTB)
#define GSMEM (2 * STG * 2)

__device__ __forceinline__ void cvt_split4(const float4 v, uint32_t& h01, uint32_t& h23,
                                           uint32_t& l01, uint32_t& l23) {
    bf16 h0 = __float2bfloat16(v.x);
    bf16 h1 = __float2bfloat16(v.y);
    bf16 h2 = __float2bfloat16(v.z);
    bf16 h3 = __float2bfloat16(v.w);
    bf16 l0 = __float2bfloat16(v.x - __bfloat162float(h0));
    bf16 l1 = __float2bfloat16(v.y - __bfloat162float(h1));
    bf16 l2 = __float2bfloat16(v.z - __bfloat162float(h2));
    bf16 l3 = __float2bfloat16(v.w - __bfloat162float(h3));
    __nv_bfloat162 H01 = {h0, h1}, H23 = {h2, h3}, L01 = {l0, l1}, L23 = {l2, l3};
    h01 = *(uint32_t*)&H01; h23 = *(uint32_t*)&H23;
    l01 = *(uint32_t*)&L01; l23 = *(uint32_t*)&L23;
}

#define MMA_BF16(acc, a, b) \
    asm volatile( \
        "mma.sync.aligned.m16n8k16.row.col.f32.bf16.bf16.f32 " \
        "{%0,%1,%2,%3}, {%4,%5,%6,%7}, {%8,%9}, {%0,%1,%2,%3};" \
        : "+f"((acc)[0]), "+f"((acc)[1]), "+f"((acc)[2]), "+f"((acc)[3]) \
        : "r"((a)[0]), "r"((a)[1]), "r"((a)[2]), "r"((a)[3]), \
          "r"((b)[0]), "r"((b)[1]))

#define LDM_X4(r, addr) \
    asm volatile("ldmatrix.sync.aligned.m8n8.x4.shared.b16 {%0,%1,%2,%3}, [%4];" \
        : "=r"((r)[0]), "=r"((r)[1]), "=r"((r)[2]), "=r"((r)[3]) : "r"(addr))
#define LDM_X2(r, addr) \
    asm volatile("ldmatrix.sync.aligned.m8n8.x2.shared.b16 {%0,%1}, [%2];" \
        : "=r"((r)[0]), "=r"((r)[1]) : "r"(addr))

__global__ void __launch_bounds__(256, 2) gemm_bf16x3(
    const float* __restrict__ A, const float* __restrict__ BT,
    const float* __restrict__ bias, float* __restrict__ Cout,
    __half* __restrict__ Cout16,
    int N, int K, size_t a_bstride, size_t c_bstride)
{
    extern __shared__ __align__(16) bf16 smem[];

    const int tid = threadIdx.x;
    const int warp = tid >> 5, lane = tid & 31;
    const int g = lane >> 2, t = lane & 3;
    const int warpM = (warp >> 1) * 32;
    const int warpN = (warp & 1) * 32;
    const int m0 = blockIdx.x * 128, n0 = blockIdx.y * 64;
    const float* Ab = A + blockIdx.z * a_bstride;

    const int lrow = tid >> 3;
    const int lkq  = (tid & 7) << 2;

    const int aRow = (lane & 7) + ((lane >> 3) & 1) * 8;
    const int aK8  = (lane >> 4) * 8;
    const int bRow = lane & 7;
    const int bK8  = ((lane >> 3) & 1) * 8;

    const uint32_t smem_base = (uint32_t)__cvta_generic_to_shared(smem);
    const uint32_t aLaneOff = (uint32_t)((warpM + aRow) * KPB + aK8) * 2;
    const uint32_t bLaneOff = (uint32_t)((warpN + bRow) * KPB + bK8) * 2;

    float acc[2][4][4];
    #pragma unroll
    for (int a = 0; a < 2; a++)
        #pragma unroll
        for (int b = 0; b < 4; b++)
            #pragma unroll
            for (int c = 0; c < 4; c++) acc[a][b][c] = 0.f;

    const int ntiles = K / KC;
    float4 pa[4], pb[2];

    #pragma unroll
    for (int j = 0; j < 4; j++)
        pa[j] = __ldg((const float4*)(Ab + (size_t)(m0 + lrow + j * 32) * K + lkq));
    #pragma unroll
    for (int j = 0; j < 2; j++)
        pb[j] = __ldg((const float4*)(BT + (size_t)(n0 + lrow + j * 32) * K + lkq));
    {
        bf16* st = smem;
        #pragma unroll
        for (int j = 0; j < 4; j++) {
            const int off = (lrow + j * 32) * KPB + lkq;
            uint32_t h01, h23, l01, l23;
            cvt_split4(pa[j], h01, h23, l01, l23);
            *(uint2*)(st + OFF_AH + off) = make_uint2(h01, h23);
            *(uint2*)(st + OFF_AL + off) = make_uint2(l01, l23);
        }
        #pragma unroll
        for (int j = 0; j < 2; j++) {
            const int off = (lrow + j * 32) * KPB + lkq;
            uint32_t h01, h23, l01, l23;
            cvt_split4(pb[j], h01, h23, l01, l23);
            *(uint2*)(st + OFF_BH + off) = make_uint2(h01, h23);
            *(uint2*)(st + OFF_BL + off) = make_uint2(l01, l23);
        }
    }
    __syncthreads();

    int cur = 0;
    for (int i = 0; i < ntiles; i++) {
        if (i + 1 < ntiles) {
            const int k0 = (i + 1) * KC;
            #pragma unroll
            for (int j = 0; j < 4; j++)
                pa[j] = __ldg((const float4*)(Ab + (size_t)(m0 + lrow + j * 32) * K + k0 + lkq));
            #pragma unroll
            for (int j = 0; j < 2; j++)
                pb[j] = __ldg((const float4*)(BT + (size_t)(n0 + lrow + j * 32) * K + k0 + lkq));
        }

        const uint32_t stg = smem_base + (uint32_t)(cur * STG) * 2;
        const uint32_t AhB = stg + aLaneOff;
        const uint32_t AlB = AhB + OFF_AL * 2;
        const uint32_t BhB = stg + OFF_BH * 2 + bLaneOff;
        const uint32_t BlB = stg + OFF_BL * 2 + bLaneOff;

        uint32_t ah[2][4], al[2][4], bh[4][2], bl[4][2];

        #pragma unroll
        for (int mt = 0; mt < 2; mt++) {
            const uint32_t mo = (uint32_t)(mt * 16 * KPB) * 2;
            LDM_X4(ah[mt], AhB + mo);
            LDM_X4(al[mt], AlB + mo);
        }
        #pragma unroll
        for (int nt = 0; nt < 4; nt++) {
            const uint32_t no = (uint32_t)(nt * 8 * KPB) * 2;
            LDM_X2(bh[nt], BhB + no);
            LDM_X2(bl[nt], BlB + no);
        }
        #pragma unroll
        for (int mt = 0; mt < 2; mt++)
            #pragma unroll
            for (int nt = 0; nt < 4; nt++) {
                MMA_BF16(acc[mt][nt], ah[mt], bh[nt]);
                MMA_BF16(acc[mt][nt], ah[mt], bl[nt]);
                MMA_BF16(acc[mt][nt], al[mt], bh[nt]);
            }

        uint32_t ah1[2][4], al1[2][4], bh1[4][2], bl1[4][2];
        #pragma unroll
        for (int mt = 0; mt < 2; mt++) {
            const uint32_t mo = (uint32_t)(mt * 16 * KPB) * 2 + 32;
            LDM_X4(ah1[mt], AhB + mo);
            LDM_X4(al1[mt], AlB + mo);
        }
        #pragma unroll
        for (int nt = 0; nt < 4; nt++) {
            const uint32_t no = (uint32_t)(nt * 8 * KPB) * 2 + 32;
            LDM_X2(bh1[nt], BhB + no);
            LDM_X2(bl1[nt], BlB + no);
        }

        if (i + 1 < ntiles) {
            bf16* st = smem + (cur ^ 1) * STG;
            #pragma unroll
            for (int j = 0; j < 4; j++) {
                const int off = (lrow + j * 32) * KPB + lkq;
                uint32_t h01, h23, l01, l23;
                cvt_split4(pa[j], h01, h23, l01, l23);
                *(uint2*)(st + OFF_AH + off) = make_uint2(h01, h23);
                *(uint2*)(st + OFF_AL + off) = make_uint2(l01, l23);
            }
            #pragma unroll
            for (int j = 0; j < 2; j++) {
                const int off = (lrow + j * 32) * KPB + lkq;
                uint32_t h01, h23, l01, l23;
                cvt_split4(pb[j], h01, h23, l01, l23);
                *(uint2*)(st + OFF_BH + off) = make_uint2(h01, h23);
                *(uint2*)(st + OFF_BL + off) = make_uint2(l01, l23);
            }
        }

        #pragma unroll
        for (int mt = 0; mt < 2; mt++)
            #pragma unroll
            for (int nt = 0; nt < 4; nt++) {
                MMA_BF16(acc[mt][nt], ah1[mt], bh1[nt]);
                MMA_BF16(acc[mt][nt], ah1[mt], bl1[nt]);
                MMA_BF16(acc[mt][nt], al1[mt], bh1[nt]);
            }

        __syncthreads();
        cur ^= 1;
    }

    if (Cout16) {
        __half* Cb = Cout16 + blockIdx.z * c_bstride;
        #pragma unroll
        for (int mt = 0; mt < 2; mt++) {
            const int r0 = m0 + warpM + mt * 16 + g;
            #pragma unroll
            for (int nt = 0; nt < 4; nt++) {
                const int cc = n0 + warpN + nt * 8 + 2 * t;
                __half2 o0 = __floats2half2_rn(acc[mt][nt][0], acc[mt][nt][1]);
                __half2 o1 = __floats2half2_rn(acc[mt][nt][2], acc[mt][nt][3]);
                *(uint32_t*)(Cb + (size_t)r0 * N + cc)       = *(uint32_t*)&o0;
                *(uint32_t*)(Cb + (size_t)(r0 + 8) * N + cc) = *(uint32_t*)&o1;
            }
        }
    } else {
        float* Cb = Cout + blockIdx.z * c_bstride;
        #pragma unroll
        for (int mt = 0; mt < 2; mt++) {
            const int r0 = m0 + warpM + mt * 16 + g;
            #pragma unroll
            for (int nt = 0; nt < 4; nt++) {
                const int cc = n0 + warpN + nt * 8 + 2 * t;
                float b0 = bias ? bias[cc] : 0.f;
                float b1 = bias ? bias[cc + 1] : 0.f;
                float2 o0 = make_float2(acc[mt][nt][0] + b0, acc[mt][nt][1] + b1);
                float2 o1 = make_float2(acc[mt][nt][2] + b0, acc[mt][nt][3] + b1);
                *(float2*)(Cb + (size_t)r0 * N + cc)       = o0;
                *(float2*)(Cb + (size_t)(r0 + 8) * N + cc) = o1;
            }
        }
    }
}

// ============================================================
// Softmax + bilinear gather. v is fp16: one half2 load per corner per lane.
// Lane handles dh = {2*lane, 2*lane+1}.
// ============================================================
__global__ void sample_kernel(const float* __restrict__ ref_xy)
{
    const int bt = blockIdx.x;
    const int b  = bt >> 11;
    const int h  = threadIdx.x >> 5;
    const int lane = threadIdx.x & 31;

    const __half* vb = g_v + (size_t)b * HW_ * D_;
    const float rx = ref_xy[(size_t)bt * 2 + 0];
    const float ry = ref_xy[(size_t)bt * 2 + 1];

    const float* pr = g_proj + (size_t)bt * NQ_;

    float wv = -INFINITY, ox = 0.f, oy = 0.f;
    if (lane < P_) {
        wv = pr[256 + h * P_ + lane];
        ox = pr[(h * P_ + lane) * 2 + 0];
        oy = pr[(h * P_ + lane) * 2 + 1];
    }
    float m = wv;
    #pragma unroll
    for (int o = 8; o >= 1; o >>= 1) m = fmaxf(m, __shfl_xor_sync(0xffffffffu, m, o));
    float e = (lane < P_) ? __expf(wv - m) : 0.f;
    float s = e;
    #pragma unroll
    for (int o = 8; o >= 1; o >>= 1) s += __shfl_xor_sync(0xffffffffu, s, o);
    const float aw = (lane < P_) ? (e / s) : 0.f;

    const float ix = (rx + RADIUS_ * ox) * (float)(WF_ - 1);
    const float iy = (ry + RADIUS_ * oy) * (float)(HF_ - 1);
    const float fx0 = floorf(ix), fy0 = floorf(iy);
    const int   x0 = (int)fx0,   y0 = (int)fy0;
    const float fx = ix - fx0,   fy = iy - fy0;

    int   idxc[4];
    float wc[4];
    {
        const int x1 = x0 + 1, y1 = y0 + 1;
        const int xs[4] = {x0, x1, x0, x1};
        const int ys[4] = {y0, y0, y1, y1};
        const float ww[4] = {(1.f - fx) * (1.f - fy), fx * (1.f - fy),
                             (1.f - fx) * fy,         fx * fy};
        #pragma unroll
        for (int c = 0; c < 4; c++) {
            const bool valid = (xs[c] >= 0) & (xs[c] < WF_) & (ys[c] >= 0) & (ys[c] < HF_);
            const int xc = min(max(xs[c], 0), WF_ - 1);
            const int yc = min(max(ys[c], 0), HF_ - 1);
            idxc[c] = yc * WF_ + xc;
            wc[c]   = valid ? (ww[c] * aw) : 0.f;
        }
    }

    float acc0 = 0.f, acc1 = 0.f;       // dh = 2*lane, 2*lane+1
    const int hbase = h * DH_;
    #pragma unroll 4
    for (int p = 0; p < P_; p++) {
        #pragma unroll
        for (int c = 0; c < 4; c++) {
            const int   idx = __shfl_sync(0xffffffffu, idxc[c], p);
            const float w   = __shfl_sync(0xffffffffu, wc[c],   p);
            if (w != 0.f) {
                const __half2 vv =
                    ((const __half2*)(vb + (size_t)idx * D_ + hbase))[lane];
                const float2 vf = __half22float2(vv);
                acc0 += w * vf.x;
                acc1 += w * vf.y;
            }
        }
    }
    float* cp = g_ctx + (size_t)bt * D_ + hbase;
    *(float2*)(cp + 2 * lane) = make_float2(acc0, acc1);
}

// ============================================================
extern "C" void kernel_launch(void* const* d_in, const int* in_sizes, int n_in,
                              void* d_out, int out_size)
{
    const float* q      = (const float*)d_in[0];
    const float* fmap   = (const float*)d_in[1];
    const float* ref_xy = (const float*)d_in[2];
    const float* Wv     = (const float*)d_in[3];
    const float* W_off  = (const float*)d_in[4];
    const float* b_off  = (const float*)d_in[5];
    const float* W_w    = (const float*)d_in[6];
    const float* b_w    = (const float*)d_in[7];
    const float* W_out  = (const float*)d_in[8];
    const float* b_out  = (const float*)d_in[9];
    float* out = (float*)d_out;

    float *proj, *ctx, *fmapT, *WvT, *WoutT, *WqT, *bq;
    __half *v;
    cudaGetSymbolAddress((void**)&v,     g_v);
    cudaGetSymbolAddress((void**)&proj,  g_proj);
    cudaGetSymbolAddress((void**)&ctx,   g_ctx);
    cudaGetSymbolAddress((void**)&fmapT, g_fmapT);
    cudaGetSymbolAddress((void**)&WvT,   g_WvT);
    cudaGetSymbolAddress((void**)&WoutT, g_WoutT);
    cudaGetSymbolAddress((void**)&WqT,   g_WqT);
    cudaGetSymbolAddress((void**)&bq,    g_bq);

    cudaFuncSetAttribute(gemm_bf16x3, cudaFuncAttributeMaxDynamicSharedMemorySize, GSMEM);

    // L1: fmap [B,C,HW] -> fmapT [B,HW,C]
    transpose_kernel<<<dim3(HW_ / 32, C_ / 32, B_), dim3(32, 8)>>>(fmap, fmapT, C_, HW_);
    // L2: weight transposes + bias concat
    prep_weights<<<dim3(16, 16, 4), dim3(32, 8)>>>(Wv, W_out, W_off, W_w, b_off, b_w);

    // L3 (K1): v[b] = fmapT[b] @ Wv  -> fp16 output
    gemm_bf16x3<<<dim3(HW_ / 128, D_ / 64, B_), 256, GSMEM>>>(
        fmapT, WvT, (const float*)0, (float*)0, v, D_, C_,
        (size_t)HW_ * C_, (size_t)HW_ * D_);

    // L4 (K2): proj = q @ [W_off|W_w] + bias  -> fp32
    gemm_bf16x3<<<dim3(M_BT / 128, NQ_ / 64, 1), 256, GSMEM>>>(
        q, WqT, bq, proj, (__half*)0, NQ_, D_, 0, 0);

    // L5: softmax + bilinear gather -> ctx
    sample_kernel<<<M_BT, H_ * 32>>>(ref_xy);

    // L6 (K4): out = ctx @ W_out + b_out  -> fp32
    gemm_bf16x3<<<dim3(M_BT / 128, D_ / 64, 1), 256, GSMEM>>>(
        ctx, WoutT, b_out, out, (__half*)0, D_, D_, 0, 0);
}